// round 16
// baseline (speedup 1.0000x reference)
#include <cuda_runtime.h>
#include <cuda_fp16.h>
#include <math.h>
#include <stdint.h>

#define B_   16
#define H_   32
#define Wd_  32
#define CI   8
#define AI   32
#define CO   16
#define AO   16
#define COAO 256

// votes scratch (fp16) [pix][ci][co*ao] = 33.5M halves = 64 MiB
__device__ __half g_vh[(size_t)B_ * H_ * Wd_ * CI * COAO];
// fp16 fragment-order weights: [tap 25][kstep 2][nt 32][lane 32][4 halves]
__device__ __half g_Bh[25 * 2 * 32 * 32 * 4];   // 400 KB

// ---- SMEM layout (bytes) --------------------------------------------------
// patch: 288 entries (8 halo rows x 36 cols) x 40 halves (32 atoms + 8 pad)
//   entry stride 40 halves = 20 words -> A-frag banks (20r + q) mod 32 distinct
#define PATCH_BYTES (288 * 40 * 2)      // 23040
#define BBUF_BYTES  16384               // one tap of fp16 B fragments
#define NBUF        3
#define SMEM_BYTES  (PATCH_BYTES + NBUF * BBUF_BYTES)   // 72192

__device__ __forceinline__ void cp16(void* dst, const void* src) {
    unsigned d = (unsigned)__cvta_generic_to_shared(dst);
    asm volatile("cp.async.cg.shared.global [%0], [%1], 16;" :: "r"(d), "l"(src));
}
__device__ __forceinline__ uint32_t h2u(__half2 h) {
    return *(uint32_t*)&h;
}

#define MMA16(d, A, b0, b1) \
    asm volatile( \
        "mma.sync.aligned.m16n8k16.row.col.f32.f16.f16.f32 " \
        "{%0,%1,%2,%3}, {%4,%5,%6,%7}, {%8,%9}, {%0,%1,%2,%3};" \
        : "+f"((d)[0]), "+f"((d)[1]), "+f"((d)[2]), "+f"((d)[3]) \
        : "r"((A)[0]), "r"((A)[1]), "r"((A)[2]), "r"((A)[3]), \
          "r"(b0), "r"(b1))

// ---------------------------------------------------------------------------
// Precompute fp16 fragment-order weights.
// ---------------------------------------------------------------------------
__global__ void __launch_bounds__(256)
bfrag_kernel(const float* __restrict__ W) {
    const int tap = blockIdx.x;          // 0..24
    const int nt  = blockIdx.y;          // 0..31
    const int t   = threadIdx.x;
    const int ks   = t >> 7;             // kstep 0..1
    const int rem  = t & 127;
    const int lane = rem >> 2;           // 0..31
    const int h4   = rem & 3;            // half slot within lane
    const int q = lane & 3, r = lane >> 2;
    const int j = h4 >> 1, h = h4 & 1;
    const int k = ks * 16 + 2 * q + 8 * j + h;
    const int n = nt * 8 + r;
    g_Bh[(((tap * 2 + ks) * 32 + nt) * 32 + lane) * 4 + h4] =
        __float2half_rn(W[(tap * 32 + k) * COAO + n]);
}

// ---------------------------------------------------------------------------
// Conv kernel: fp16 m16n8k16 mma.sync GEMM (fp32 accum), fp16 votes out.
// CTA = (hq, ci, b): M = 4h x 32w = 128, N = 256. 8 warps 2(M) x 4(N),
// warp tile 64x64. Per tap: batch-load ALL 48 fragments into regs (fully
// independent LDS stream), then 64 back-to-back MMAs.
// ---------------------------------------------------------------------------
__global__ void __launch_bounds__(256, 1)
conv_kernel(const float* __restrict__ x) {
    extern __shared__ char smem[];
    uint32_t*   patch_w = (uint32_t*)smem;            // patch as words (half2)
    char*       bbuf    = smem + PATCH_BYTES;

    const int tid = threadIdx.x;
    const int wid = tid >> 5, lid = tid & 31;
    const int hq = blockIdx.x, ci = blockIdx.y, b = blockIdx.z;
    const int h0 = hq * 4;

    // ---- prefetch B taps 0 and 1 ----
    #pragma unroll
    for (int tp = 0; tp < 2; ++tp) {
        const __half* src = g_Bh + (size_t)tp * 8192;
        char* dst = bbuf + tp * BBUF_BYTES;
        #pragma unroll
        for (int ii = 0; ii < 4; ++ii) {
            int i = tid + ii * 256;
            cp16(dst + i * 16, src + i * 8);
        }
        asm volatile("cp.async.commit_group;");
    }

    // ---- load halo patch (fp16): rows h0-2..h0+5, cols -2..33, 32 atoms ----
    #pragma unroll
    for (int ii = 0; ii < 9; ++ii) {
        int i   = tid + ii * 256;                     // 0..2303
        int a4  = i & 7;                              // atom group (4 atoms)
        int e   = i >> 3;                             // entry = hi*36 + ww
        int ww  = e % 36;
        int hi  = e / 36;
        int hg  = h0 + hi - 2, wg = ww - 2;
        float4 v = make_float4(0.f, 0.f, 0.f, 0.f);
        if ((unsigned)hg < 32u && (unsigned)wg < 32u)
            v = *(const float4*)(x + ((((size_t)(b * 32 + hg) * 32 + wg) * CI
                                       + ci) * AI + a4 * 4));
        uint2 hv;
        hv.x = h2u(__floats2half2_rn(v.x, v.y));
        hv.y = h2u(__floats2half2_rn(v.z, v.w));
        *(uint2*)((char*)smem + e * 80 + a4 * 8) = hv;
    }

    const int wm = wid >> 2, wn = wid & 3;            // warp M/N coords
    const int r = lid >> 2, q = lid & 3;

    int ebase[4];
    #pragma unroll
    for (int mt = 0; mt < 4; ++mt) {
        int m0   = wm * 64 + mt * 16;                 // m = hi2*32 + w
        ebase[mt] = (m0 >> 5) * 36 + (m0 & 31) + r;
    }

    float acc[4][8][4];
    #pragma unroll
    for (int mt = 0; mt < 4; ++mt)
        #pragma unroll
        for (int nt = 0; nt < 8; ++nt)
            #pragma unroll
            for (int k = 0; k < 4; ++k) acc[mt][nt][k] = 0.f;

    #pragma unroll 1
    for (int t = 0; t < 25; ++t) {
        if (t >= 23) asm volatile("cp.async.wait_group 0;");
        else         asm volatile("cp.async.wait_group 1;");
        __syncthreads();

        if (t + 2 < 25) {   // prefetch tap t+2 (DRAM/L2 latency overlaps MMAs)
            const __half* src = g_Bh + (size_t)(t + 2) * 8192;
            char* dst = bbuf + ((t + 2) % NBUF) * BBUF_BYTES;
            #pragma unroll
            for (int ii = 0; ii < 4; ++ii) {
                int i = tid + ii * 256;
                cp16(dst + i * 16, src + i * 8);
            }
            asm volatile("cp.async.commit_group;");
        }

        const int dy = t / 5, dx = t % 5;
        const int eoff = dy * 36 + dx;
        const char* bb = bbuf + (t % NBUF) * BBUF_BYTES;

        // ---- batch-load ALL fragments for this tap (48 independent LDS) ----
        uint2 bf[2][8];
        #pragma unroll
        for (int ks = 0; ks < 2; ++ks)
            #pragma unroll
            for (int nt = 0; nt < 8; ++nt)
                bf[ks][nt] = *(const uint2*)(bb +
                    (((ks * 32 + wn * 8 + nt) * 32 + lid) << 3));

        uint32_t A[2][4][4];
        #pragma unroll
        for (int ks = 0; ks < 2; ++ks)
            #pragma unroll
            for (int mt = 0; mt < 4; ++mt) {
                const uint32_t* p = patch_w + (ebase[mt] + eoff) * 20
                                  + ks * 8 + q;
                A[ks][mt][0] = p[0];
                A[ks][mt][1] = p[160];   // row r+8 (entry +8 -> +160 words)
                A[ks][mt][2] = p[4];     // k +8
                A[ks][mt][3] = p[164];
            }

        // ---- 64 back-to-back MMAs ----
        #pragma unroll
        for (int ks = 0; ks < 2; ++ks)
            #pragma unroll
            for (int mt = 0; mt < 4; ++mt)
                #pragma unroll
                for (int nt = 0; nt < 8; ++nt)
                    MMA16(acc[mt][nt], A[ks][mt], bf[ks][nt].x, bf[ks][nt].y);
    }

    // ---- epilogue: votes as fp16 (half2 packs from accumulator pairs) ----
    #pragma unroll
    for (int mt = 0; mt < 4; ++mt) {
        int m   = wm * 64 + mt * 16 + r;
        int hi2 = m >> 5, w = m & 31;
        size_t base0 = (((size_t)(b * 32 + h0 + hi2)) * 32 + w) * 2048
                     + ci * 256 + wn * 64 + 2 * q;          // half index
        size_t base1 = base0 + 8 * 2048;
        #pragma unroll
        for (int nt = 0; nt < 8; ++nt) {
            *(__half2*)(g_vh + base0 + nt * 8) =
                __floats2half2_rn(acc[mt][nt][0], acc[mt][nt][1]);
            *(__half2*)(g_vh + base1 + nt * 8) =
                __floats2half2_rn(acc[mt][nt][2], acc[mt][nt][3]);
        }
    }
}

// ---------------------------------------------------------------------------
// Routing kernel v3: 4 pixels/CTA, fp16 votes, vectorized over ao-quads.
// thread t: pixL = t>>6, j = t&63, co = j>>2, aq = j&3 (ao = aq*4..aq*4+3).
// ---------------------------------------------------------------------------
__global__ void __launch_bounds__(256)
routing_kernel(const float* __restrict__ bias, float* __restrict__ out) {
    __shared__ float lg[512];   // [pixL 4][ci 8][co 16]
    __shared__ float rt[512];

    const int t = threadIdx.x;
    const int pixL = t >> 6, j = t & 63;
    const int co = j >> 2;
    const size_t pix = (size_t)blockIdx.x * 4 + pixL;

    // votes: 8 coalesced 8B loads (4 halves each)
    float v[8][4];
    const __half* vp = g_vh + pix * 2048 + j * 4;   // co*16 + aq*4 == j*4
    #pragma unroll
    for (int c = 0; c < 8; ++c) {
        uint2 u = *(const uint2*)(vp + c * 256);
        float2 f0 = __half22float2(*(__half2*)&u.x);
        float2 f1 = __half22float2(*(__half2*)&u.y);
        v[c][0] = f0.x; v[c][1] = f0.y; v[c][2] = f1.x; v[c][3] = f1.y;
    }
    const float4 bb = ((const float4*)bias)[j];
    lg[t] = 0.f; lg[t + 256] = 0.f;
    __syncthreads();

    float a0 = 0.f, a1 = 0.f, a2 = 0.f, a3 = 0.f;
    #pragma unroll 1
    for (int it = 0; it < 3; ++it) {
        // softmax over co: entries t and t+256 (co = t&15 -> width-16 shuffles)
        {
            float l0 = lg[t], l1 = lg[t + 256];
            float m0 = l0, m1 = l1;
            #pragma unroll
            for (int o = 8; o; o >>= 1) {
                m0 = fmaxf(m0, __shfl_xor_sync(0xffffffffu, m0, o, 16));
                m1 = fmaxf(m1, __shfl_xor_sync(0xffffffffu, m1, o, 16));
            }
            float e0 = __expf(l0 - m0), e1 = __expf(l1 - m1);
            float s0 = e0, s1 = e1;
            #pragma unroll
            for (int o = 8; o; o >>= 1) {
                s0 += __shfl_xor_sync(0xffffffffu, s0, o, 16);
                s1 += __shfl_xor_sync(0xffffffffu, s1, o, 16);
            }
            rt[t] = e0 / s0; rt[t + 256] = e1 / s1;
        }
        __syncthreads();

        float p0 = bb.x, p1 = bb.y, p2 = bb.z, p3 = bb.w;
        #pragma unroll
        for (int c = 0; c < 8; ++c) {
            float rv = rt[pixL * 128 + c * 16 + co];
            p0 += rv * v[c][0]; p1 += rv * v[c][1];
            p2 += rv * v[c][2]; p3 += rv * v[c][3];
        }

        // squash: norm over 16 ao = 4 in-thread + width-4 butterfly (aq = lane&3)
        float ns = p0 * p0 + p1 * p1 + p2 * p2 + p3 * p3;
        ns += __shfl_xor_sync(0xffffffffu, ns, 1);
        ns += __shfl_xor_sync(0xffffffffu, ns, 2);
        float sq = sqrtf(ns) / (1.0f + ns);
        a0 = p0 * sq; a1 = p1 * sq; a2 = p2 * sq; a3 = p3 * sq;

        if (it < 2) {
            #pragma unroll
            for (int c = 0; c < 8; ++c) {
                float sc = v[c][0] * a0 + v[c][1] * a1
                         + v[c][2] * a2 + v[c][3] * a3;
                sc += __shfl_xor_sync(0xffffffffu, sc, 1);
                sc += __shfl_xor_sync(0xffffffffu, sc, 2);
                if ((j & 3) == 0) lg[pixL * 128 + c * 16 + co] += sc;
            }
            __syncthreads();
        }
    }
    ((float4*)out)[pix * 64 + j] = make_float4(a0, a1, a2, a3);
}

// ---------------------------------------------------------------------------
extern "C" void kernel_launch(void* const* d_in, const int* in_sizes, int n_in,
                              void* d_out, int out_size) {
    const float* x  = (const float*)d_in[0];   // [16,32,32,8,32]
    const float* Wg = (const float*)d_in[1];   // [5,5,32,256]
    const float* bb = (const float*)d_in[2];   // [1,1,16,16]
    float* out = (float*)d_out;                // [16,32,32,16,16]

    cudaFuncSetAttribute(conv_kernel,
                         cudaFuncAttributeMaxDynamicSharedMemorySize, SMEM_BYTES);

    bfrag_kernel<<<dim3(25, 32), 256>>>(Wg);
    conv_kernel<<<dim3(8, CI, B_), 256, SMEM_BYTES>>>(x);
    routing_kernel<<<B_ * H_ * Wd_ / 4, 256>>>(bb, out);
}